// round 1
// baseline (speedup 1.0000x reference)
#include <cuda_runtime.h>

// CRF NLL, B=256, S=256, T=128 (126 tags + START/STOP)
// Reformulated forward recursion: new_p = m + log(E^T · exp(p-m)) + feat
// with E = exp(transitions) precomputed in shared memory (transposed, padded).

#define B_   256
#define S_   256
#define T_   128
#define TP_  132   // padded row stride for conflict-free column access

__device__ float g_partial[B_];

__device__ __forceinline__ float warpMax(float x) {
#pragma unroll
    for (int o = 16; o; o >>= 1) x = fmaxf(x, __shfl_xor_sync(0xffffffffu, x, o));
    return x;
}
__device__ __forceinline__ float warpSum(float x) {
#pragma unroll
    for (int o = 16; o; o >>= 1) x += __shfl_xor_sync(0xffffffffu, x, o);
    return x;
}

__global__ void __launch_bounds__(128, 2) crf_kernel(
    const float* __restrict__ feats,       // [B, S, T]
    const float* __restrict__ trans,       // [T, T]
    const void*  __restrict__ tags_raw,    // [B, S] int64 OR int32 (auto-detected)
    const int*   __restrict__ mask)        // [B, S] prefix mask
{
    extern __shared__ float smem[];
    float* ET  = smem;                 // [T_ * TP_]  ET[j*TP_+i] = exp(trans[i][j])
    float* v   = smem + T_ * TP_;      // [T_]
    float* red = v + T_;               // [8]

    const int b    = blockIdx.x;
    const int tid  = threadIdx.x;
    const int lane = tid & 31;
    const int wid  = tid >> 5;
    const int START = T_ - 2, STOP = T_ - 1;

    // ---- detect tags dtype (int64 from jax-x64, or silently-demoted int32) ----
    // For int64 data the odd 32-bit words are high words == 0 always.
    // For int32 data they are random tags in [0,126): P(all 16 zero) ~ 1e-34.
    int is64;
    {
        const int* t32 = (const int*)tags_raw;
        int bad = 0;
#pragma unroll
        for (int k = 0; k < 16; ++k) bad |= t32[2 * k + 1];
        is64 = (bad == 0);
    }

    // ---- build ET = exp(trans)^T in shared (exp(-1000) underflows to 0) ----
    for (int idx = tid; idx < T_ * T_; idx += 128) {
        int i = idx >> 7, j = idx & (T_ - 1);
        ET[j * TP_ + i] = __expf(trans[idx]);
    }

    const float* fb = feats + (size_t)b * (S_ * T_);
    const int*   mb = mask + b * S_;

    // initial partition: p[j] = feats[b,0,j] + trans[START,j]
    float p = fb[tid] + trans[START * T_ + tid];
    float fnext = fb[T_ + tid];   // prefetch feat for t=1
    int   mnext = mb[1];
    __syncthreads();

    int len = S_;
    const float* etrow = ET + tid * TP_;

    for (int t = 1; t < S_; ++t) {
        if (!mnext) { len = t; break; }     // prefix mask -> uniform break
        float f = fnext;
        int tn = t + 1;
        if (tn < S_) { fnext = fb[tn * T_ + tid]; mnext = mb[tn]; }

        // block max of p
        float m = warpMax(p);
        if (lane == 0) red[wid] = m;
        __syncthreads();                    // also guards v reuse from prev iter
        m = fmaxf(fmaxf(red[0], red[1]), fmaxf(red[2], red[3]));

        v[tid] = __expf(p - m);
        __syncthreads();

        // matvec: s = sum_i v[i] * E[i][tid]
        float s = 0.f;
#pragma unroll
        for (int i4 = 0; i4 < T_ / 4; ++i4) {
            float4 e = *reinterpret_cast<const float4*>(etrow + i4 * 4);
            float4 x = *reinterpret_cast<const float4*>(v + i4 * 4);
            s = fmaf(x.x, e.x, s);
            s = fmaf(x.y, e.y, s);
            s = fmaf(x.z, e.z, s);
            s = fmaf(x.w, e.w, s);
        }
        p = m + __logf(s) + f;
    }

    // ---- final: forward_b = logsumexp_i(p_i + trans[i,STOP]) ----
    float m = warpMax(p);
    if (lane == 0) red[wid] = m;
    __syncthreads();
    m = fmaxf(fmaxf(red[0], red[1]), fmaxf(red[2], red[3]));
    float term = __expf(p - m) * ET[STOP * TP_ + tid];   // i = tid contribution
    float ssum = warpSum(term);
    if (lane == 0) red[4 + wid] = ssum;
    __syncthreads();
    float fwd = m + __logf(red[4] + red[5] + red[6] + red[7]);

    // ---- gold path score ----
    const long long* t64 = (const long long*)tags_raw;
    const int*       t32 = (const int*)tags_raw;
    const size_t tbase = (size_t)b * S_;
    float g = 0.f;
    for (int t = tid; t < S_; t += 128) {
        if (mb[t]) {
            int tag  = is64 ? (int)t64[tbase + t] : t32[tbase + t];
            int prev = (t == 0) ? START
                                : (is64 ? (int)t64[tbase + t - 1] : t32[tbase + t - 1]);
            g += fb[t * T_ + tag] + trans[prev * T_ + tag];
        }
    }
    g = warpSum(g);
    __syncthreads();                         // order vs red[4..7] reads above
    if (lane == 0) red[wid] = g;
    __syncthreads();

    if (tid == 0) {
        int end_id = is64 ? (int)t64[tbase + len - 1] : t32[tbase + len - 1];
        float gold = red[0] + red[1] + red[2] + red[3]
                   + trans[end_id * T_ + STOP];
        g_partial[b] = fwd - gold;
    }
}

// Deterministic tree reduction of the 256 per-batch partials.
__global__ void reduce_kernel(float* __restrict__ out) {
    __shared__ float sb[8];
    int tid = threadIdx.x;
    float x = g_partial[tid];
    x = warpSum(x);
    if ((tid & 31) == 0) sb[tid >> 5] = x;
    __syncthreads();
    if (tid == 0) {
        float s = 0.f;
#pragma unroll
        for (int i = 0; i < 8; ++i) s += sb[i];
        out[0] = s;
    }
}

extern "C" void kernel_launch(void* const* d_in, const int* in_sizes, int n_in,
                              void* d_out, int out_size) {
    const float* feats = (const float*)d_in[0];
    const float* trans = (const float*)d_in[1];
    const void*  tags  = d_in[2];
    const int*   mask  = (const int*)d_in[3];

    const int smem = (T_ * TP_ + T_ + 8) * (int)sizeof(float);  // 68128 B
    cudaFuncSetAttribute(crf_kernel,
                         cudaFuncAttributeMaxDynamicSharedMemorySize, smem);

    crf_kernel<<<B_, 128, smem>>>(feats, trans, tags, mask);
    reduce_kernel<<<1, 256>>>((float*)d_out);
}

// round 2
// speedup vs baseline: 2.4828x; 2.4828x over previous
#include <cuda_runtime.h>

// CRF NLL, B=256, S=256, T=128 (126 tags + START/STOP)
// Forward recursion reformulated as  p_t = mu + log(w · E) + feat_t
// with E = exp(transitions) column-resident in REGISTERS (64 packed f32x2
// per thread), w double-buffered in shared, one __syncthreads per step,
// stale-scalar normalization (no per-step block max).

#define B_   256
#define S_   256
#define T_   128

__device__ float g_partial[B_];

#define FMA2(d, a, b, c) \
    asm("fma.rn.f32x2 %0, %1, %2, %3;" : "=l"(d) : "l"(a), "l"(b), "l"(c))
#define PACK2(d, lo, hi) \
    asm("mov.b64 %0, {%1, %2};" : "=l"(d) : "f"(lo), "f"(hi))
#define UNPACK2(lo, hi, s) \
    asm("mov.b64 {%0, %1}, %2;" : "=f"(lo), "=f"(hi) : "l"(s))

__device__ __forceinline__ float warpMax(float x) {
#pragma unroll
    for (int o = 16; o; o >>= 1) x = fmaxf(x, __shfl_xor_sync(0xffffffffu, x, o));
    return x;
}
__device__ __forceinline__ float warpSum(float x) {
#pragma unroll
    for (int o = 16; o; o >>= 1) x += __shfl_xor_sync(0xffffffffu, x, o);
    return x;
}

__global__ void __launch_bounds__(128, 2) crf_kernel(
    const float* __restrict__ feats,       // [B, S, T]
    const float* __restrict__ trans,       // [T, T]
    const void*  __restrict__ tags_raw,    // [B, S] int64 OR int32 (auto-detect)
    const int*   __restrict__ mask)        // [B, S] prefix mask
{
    __shared__ __align__(16) float wb[2][132];  // [0..127]=w, [128]=mu, [129]=n
    __shared__ float red[8];

    const int b    = blockIdx.x;
    const int tid  = threadIdx.x;
    const int lane = tid & 31;
    const int wid  = tid >> 5;
    const int START = T_ - 2, STOP = T_ - 1;

    // ---- detect tags dtype (int64 from jax-x64, or silently-demoted int32) ----
    int is64;
    {
        const int* t32 = (const int*)tags_raw;
        int bad = 0;
#pragma unroll
        for (int k = 0; k < 16; ++k) bad |= t32[2 * k + 1];
        is64 = (bad == 0);
    }

    // ---- E column j=tid into registers: e[m] = {exp(tr[2m][j]), exp(tr[2m+1][j])} ----
    unsigned long long e[T_ / 2];
    {
        const float* tc = trans + tid;
#pragma unroll
        for (int m = 0; m < T_ / 2; ++m) {
            float a = __expf(tc[(2 * m) * T_]);
            float c = __expf(tc[(2 * m + 1) * T_]);
            PACK2(e[m], a, c);
        }
    }
    const float tstart = trans[START * T_ + tid];   // raw trans[START][j]
    const float tstop  = trans[tid * T_ + STOP];    // raw trans[j][STOP]

    const float* fb = feats + (size_t)b * (S_ * T_);
    const int*   mb = mask + b * S_;

    // ---- init: p0 = feat0 + trans[START], publish w0 = exp(p0 - p0[0]) ----
    float p = fb[tid] + tstart;
    if (tid == 0) red[0] = p;
    __syncthreads();
    const float m0 = red[0];
    wb[0][tid] = __expf(p - m0);
    if (tid == 0) { wb[0][128] = m0; wb[0][129] = m0; }

    float fnext = fb[T_ + tid];
    int   mnext = mb[1];
    int   buf = 0, len = S_;

    for (int t = 1; t < S_; ++t) {
        __syncthreads();                    // publishes wb[buf] (+ protects reuse)
        if (!mnext) { len = t; break; }
        float f = fnext;
        int tn = t + 1;
        if (tn < S_) { fnext = fb[tn * T_ + tid]; mnext = mb[tn]; }

        const float mu = wb[buf][128];      // normalizer used when w was written
        const float nn = wb[buf][129];      // next normalizer (stale p[0])
        const ulonglong2* wv = (const ulonglong2*)wb[buf];

        unsigned long long a0 = 0ull, a1 = 0ull;   // packed {0,0}
#pragma unroll
        for (int k = 0; k < 32; ++k) {
            ulonglong2 w2 = wv[k];          // LDS.128, broadcast across block
            FMA2(a0, w2.x, e[2 * k],     a0);
            FMA2(a1, w2.y, e[2 * k + 1], a1);
        }
        float s0, s1, s2, s3;
        UNPACK2(s0, s1, a0);
        UNPACK2(s2, s3, a1);
        float s = (s0 + s1) + (s2 + s3);

        p = mu + __logf(s) + f;             // exact absolute partition value

        buf ^= 1;
        wb[buf][tid] = __expf(p - nn);
        if (tid == 0) { wb[buf][128] = nn; wb[buf][129] = p; }
    }

    // ---- final: forward_b = logsumexp_i(p_i + trans[i, STOP]) ----
    float m = warpMax(p);
    if (lane == 0) red[wid] = m;
    __syncthreads();
    m = fmaxf(fmaxf(red[0], red[1]), fmaxf(red[2], red[3]));
    float term = __expf(p - m + tstop);     // 0 for START (-inf) and STOP (-1000)
    float ssum = warpSum(term);
    if (lane == 0) red[4 + wid] = ssum;
    __syncthreads();
    float fwd = m + __logf(red[4] + red[5] + red[6] + red[7]);

    // ---- gold path score ----
    const long long* t64 = (const long long*)tags_raw;
    const int*       t32 = (const int*)tags_raw;
    const size_t tbase = (size_t)b * S_;
    float g = 0.f;
    for (int t = tid; t < S_; t += 128) {
        if (mb[t]) {
            int tag  = is64 ? (int)t64[tbase + t] : t32[tbase + t];
            int prev = (t == 0) ? START
                                : (is64 ? (int)t64[tbase + t - 1] : t32[tbase + t - 1]);
            g += fb[t * T_ + tag] + trans[prev * T_ + tag];
        }
    }
    g = warpSum(g);
    __syncthreads();                         // order vs red[4..7] reads above
    if (lane == 0) red[wid] = g;
    __syncthreads();

    if (tid == 0) {
        int end_id = is64 ? (int)t64[tbase + len - 1] : t32[tbase + len - 1];
        float gold = red[0] + red[1] + red[2] + red[3]
                   + trans[end_id * T_ + STOP];
        g_partial[b] = fwd - gold;
    }
}

// Deterministic tree reduction of the 256 per-batch partials.
__global__ void reduce_kernel(float* __restrict__ out) {
    __shared__ float sb[8];
    int tid = threadIdx.x;
    float x = g_partial[tid];
    x = warpSum(x);
    if ((tid & 31) == 0) sb[tid >> 5] = x;
    __syncthreads();
    if (tid == 0) {
        float s = 0.f;
#pragma unroll
        for (int i = 0; i < 8; ++i) s += sb[i];
        out[0] = s;
    }
}

extern "C" void kernel_launch(void* const* d_in, const int* in_sizes, int n_in,
                              void* d_out, int out_size) {
    const float* feats = (const float*)d_in[0];
    const float* trans = (const float*)d_in[1];
    const void*  tags  = d_in[2];
    const int*   mask  = (const int*)d_in[3];

    crf_kernel<<<B_, 128>>>(feats, trans, tags, mask);
    reduce_kernel<<<1, 256>>>((float*)d_out);
}

// round 3
// speedup vs baseline: 2.6858x; 1.0818x over previous
#include <cuda_runtime.h>

// CRF NLL, B=256, S=256, T=128 (126 tags + START/STOP)
// Forward recursion in scaled-probability domain:
//   s_j = sum_i w_i * E[i][j]         (E = exp(transitions), register-resident)
//   w'_j = s_j * exp(f_j - d)         (d = scalar normalizer delta, stale-published)
//   N   += d                          (p_j = N + log w_j, recovered once at the end)
// No log/exp on the per-step critical path; exp(f-d) hides under the matvec.

#define B_   256
#define S_   256
#define T_   128

__device__ float g_partial[B_];

#define FMA2(d, a, b, c) \
    asm("fma.rn.f32x2 %0, %1, %2, %3;" : "=l"(d) : "l"(a), "l"(b), "l"(c))
#define ADD2(d, a, b) \
    asm("add.rn.f32x2 %0, %1, %2;" : "=l"(d) : "l"(a), "l"(b))
#define PACK2(d, lo, hi) \
    asm("mov.b64 %0, {%1, %2};" : "=l"(d) : "f"(lo), "f"(hi))
#define UNPACK2(lo, hi, s) \
    asm("mov.b64 {%0, %1}, %2;" : "=f"(lo), "=f"(hi) : "l"(s))

__device__ __forceinline__ float warpMax(float x) {
#pragma unroll
    for (int o = 16; o; o >>= 1) x = fmaxf(x, __shfl_xor_sync(0xffffffffu, x, o));
    return x;
}
__device__ __forceinline__ float warpSum(float x) {
#pragma unroll
    for (int o = 16; o; o >>= 1) x += __shfl_xor_sync(0xffffffffu, x, o);
    return x;
}

__global__ void __launch_bounds__(128, 2) crf_kernel(
    const float* __restrict__ feats,       // [B, S, T]
    const float* __restrict__ trans,       // [T, T]
    const void*  __restrict__ tags_raw,    // [B, S] int64 OR int32 (auto-detect)
    const int*   __restrict__ mask)        // [B, S] prefix mask
{
    __shared__ __align__(16) float wb[2][132];  // [0..127]=w, [128]=d for consumer
    __shared__ float red[8];

    const int b    = blockIdx.x;
    const int tid  = threadIdx.x;
    const int lane = tid & 31;
    const int wid  = tid >> 5;
    const int START = T_ - 2, STOP = T_ - 1;

    // ---- detect tags dtype (int64 from jax-x64, or silently-demoted int32) ----
    int is64;
    {
        const int* t32 = (const int*)tags_raw;
        int bad = 0;
#pragma unroll
        for (int k = 0; k < 16; ++k) bad |= t32[2 * k + 1];
        is64 = (bad == 0);
    }

    // ---- E column j=tid into registers: e[m] = {exp(tr[2m][j]), exp(tr[2m+1][j])} ----
    unsigned long long e[T_ / 2];
    {
        const float* tc = trans + tid;
#pragma unroll
        for (int m = 0; m < T_ / 2; ++m) {
            float a = __expf(tc[(2 * m) * T_]);
            float c = __expf(tc[(2 * m + 1) * T_]);
            PACK2(e[m], a, c);
        }
    }
    const float tstart = trans[START * T_ + tid];   // trans[START][j]
    const float tstop  = trans[tid * T_ + STOP];    // trans[j][STOP]

    const float* fb = feats + (size_t)b * (S_ * T_);
    const int*   mb = mask + b * S_;

    // ---- init: p0 = feat0 + trans[START];  w0 = exp(p0 - p0[0]);  N = p0[0] ----
    float p0 = fb[tid] + tstart;
    if (tid == 0) red[0] = p0;
    __syncthreads();
    const float m0 = red[0];
    float wreg = __expf(p0 - m0);
    wb[0][tid] = wreg;
    if (tid == 0) wb[0][128] = __logf(wreg * 128.0f);   // = log(128)
    float N = m0;

    const float* fp = fb + T_ + tid;   // prefetch ptr (t=1)
    float fnext = *fp;
    int   mnext = mb[1];
    int   buf = 0, len = S_;

    for (int t = 1; t < S_; ++t) {
        __syncthreads();                    // publishes wb[buf] (+ protects reuse)
        if (!mnext) { len = t; break; }
        float f = fnext;
        if (t + 1 < S_) { fp += T_; fnext = *fp; mnext = mb[t + 1]; }

        const float d = wb[buf][128];
        N += d;
        const float ef = __expf(f - d);     // issues early, hides under matvec
        const ulonglong2* wv = (const ulonglong2*)wb[buf];

        unsigned long long a0 = 0ull, a1 = 0ull, a2 = 0ull, a3 = 0ull;
#pragma unroll
        for (int k = 0; k < 32; k += 2) {
            ulonglong2 wA = wv[k];
            ulonglong2 wB = wv[k + 1];
            FMA2(a0, wA.x, e[2 * k],     a0);
            FMA2(a1, wA.y, e[2 * k + 1], a1);
            FMA2(a2, wB.x, e[2 * k + 2], a2);
            FMA2(a3, wB.y, e[2 * k + 3], a3);
        }
        ADD2(a0, a0, a2);
        ADD2(a1, a1, a3);
        ADD2(a0, a0, a1);
        float s0, s1;
        UNPACK2(s0, s1, a0);
        wreg = (s0 + s1) * ef;

        buf ^= 1;
        wb[buf][tid] = wreg;
        if (tid == 0) wb[buf][128] = __logf(wreg * 128.0f);  // d for next step
    }

    // ---- final: forward_b = logsumexp_i(p_i + trans[i, STOP]),  p = N + log w ----
    float p = N + __logf(wreg);             // -inf for START (w=0): fine under max
    float m = warpMax(p);
    if (lane == 0) red[wid] = m;
    __syncthreads();
    m = fmaxf(fmaxf(red[0], red[1]), fmaxf(red[2], red[3]));
    float term = wreg * __expf(N - m + tstop);   // exp(p - m + tstop), 0-safe
    float ssum = warpSum(term);
    if (lane == 0) red[4 + wid] = ssum;
    __syncthreads();
    float fwd = m + __logf(red[4] + red[5] + red[6] + red[7]);

    // ---- gold path score ----
    const long long* t64 = (const long long*)tags_raw;
    const int*       t32 = (const int*)tags_raw;
    const size_t tbase = (size_t)b * S_;
    float g = 0.f;
    for (int t = tid; t < S_; t += 128) {
        if (mb[t]) {
            int tag  = is64 ? (int)t64[tbase + t] : t32[tbase + t];
            int prev = (t == 0) ? START
                                : (is64 ? (int)t64[tbase + t - 1] : t32[tbase + t - 1]);
            g += fb[t * T_ + tag] + trans[prev * T_ + tag];
        }
    }
    g = warpSum(g);
    __syncthreads();                         // order vs red[4..7] reads above
    if (lane == 0) red[wid] = g;
    __syncthreads();

    if (tid == 0) {
        int end_id = is64 ? (int)t64[tbase + len - 1] : t32[tbase + len - 1];
        float gold = red[0] + red[1] + red[2] + red[3]
                   + trans[end_id * T_ + STOP];
        g_partial[b] = fwd - gold;
    }
}

// Deterministic tree reduction of the 256 per-batch partials.
__global__ void reduce_kernel(float* __restrict__ out) {
    __shared__ float sb[8];
    int tid = threadIdx.x;
    float x = g_partial[tid];
    x = warpSum(x);
    if ((tid & 31) == 0) sb[tid >> 5] = x;
    __syncthreads();
    if (tid == 0) {
        float s = 0.f;
#pragma unroll
        for (int i = 0; i < 8; ++i) s += sb[i];
        out[0] = s;
    }
}

extern "C" void kernel_launch(void* const* d_in, const int* in_sizes, int n_in,
                              void* d_out, int out_size) {
    const float* feats = (const float*)d_in[0];
    const float* trans = (const float*)d_in[1];
    const void*  tags  = d_in[2];
    const int*   mask  = (const int*)d_in[3];

    crf_kernel<<<B_, 128>>>(feats, trans, tags, mask);
    reduce_kernel<<<1, 256>>>((float*)d_out);
}